// round 13
// baseline (speedup 1.0000x reference)
#include <cuda_runtime.h>
#include <cuda_bf16.h>
#include <cstdint>

// Problem constants.
#define D    96      // D_IN == D_OUT
#define K2   192     // concat K = 2*D
#define MAXN 50000

// Scratch (no cudaMalloc allowed). uint4 typing guarantees 16B alignment.
__device__ float g_agg[(size_t)MAXN * D];        // neighbor-sum
__device__ float g_part[(size_t)MAXN * D];       // x@Wr^T + bl partial
__device__ float g_deg[MAXN];                    // in-degree (float)
__device__ uint4 g_Bhi4[(D * K2 * 2) / 16];      // [96][24 uint4] Wcat hi
__device__ uint4 g_Blo4[(D * K2 * 2) / 16];      // [96][24 uint4] Wcat lo

// ---------------------------------------------------------------------------
// helpers
// ---------------------------------------------------------------------------
__device__ __forceinline__ uint32_t smem_u32(const void* p) {
    uint32_t a;
    asm("{ .reg .u64 t; cvta.to.shared.u64 t, %1; cvt.u32.u64 %0, t; }"
        : "=r"(a) : "l"(p));
    return a;
}

__device__ __forceinline__ uint32_t pack_bf16x2(float a, float b) {
    uint32_t r;
    asm("cvt.rn.bf16x2.f32 %0, %1, %2;" : "=r"(r) : "f"(b), "f"(a));
    return r;
}

#define LDSM_X4(r, addr)                                                      \
    asm volatile("ldmatrix.sync.aligned.m8n8.x4.shared.b16 "                  \
                 "{%0,%1,%2,%3}, [%4];"                                       \
                 : "=r"((r)[0]), "=r"((r)[1]), "=r"((r)[2]), "=r"((r)[3])     \
                 : "r"(addr))

__device__ __forceinline__ void mma_bf16(float* c, const uint32_t* a,
                                         uint32_t b0, uint32_t b1) {
    asm volatile(
        "mma.sync.aligned.m16n8k16.row.col.f32.bf16.bf16.f32 "
        "{%0,%1,%2,%3}, {%4,%5,%6,%7}, {%8,%9}, {%0,%1,%2,%3};"
        : "+f"(c[0]), "+f"(c[1]), "+f"(c[2]), "+f"(c[3])
        : "r"(a[0]), "r"(a[1]), "r"(a[2]), "r"(a[3]), "r"(b0), "r"(b1));
}

// half-GEMM smem layout: 16-chunk (256 B) row stride, data chunks 0..11
// swizzled into slots 0..15.
#define BRS2 256
#define SM_BLO_OFF (96 * BRS2)
#define SM_HALF_TOTAL (2 * 96 * BRS2)    // 49152 B

__device__ __forceinline__ int bswz(int row, int chunk) {
    return ((chunk & ~7) | ((chunk ^ row) & 7)) << 4;
}

// ---------------------------------------------------------------------------
// 0) prep: zero agg+deg, split W = [Wl|Wr] into bf16 hi/lo
// ---------------------------------------------------------------------------
__global__ void prep_kernel(const float* __restrict__ Wl,
                            const float* __restrict__ Wr,
                            int n_agg4, int n_deg)
{
    int idx = blockIdx.x * blockDim.x + threadIdx.x;
    int stride = gridDim.x * blockDim.x;
    float4* a4 = reinterpret_cast<float4*>(g_agg);
    for (int i = idx; i < n_agg4; i += stride)
        a4[i] = make_float4(0.f, 0.f, 0.f, 0.f);
    for (int i = idx; i < n_deg; i += stride)
        g_deg[i] = 0.f;
    for (int i = idx; i < D * K2; i += stride) {
        int r = i / K2, k = i % K2;
        float w = (k < D) ? Wl[r * D + k] : Wr[r * D + (k - D)];
        __nv_bfloat16 h = __float2bfloat16(w);
        reinterpret_cast<__nv_bfloat16*>(g_Bhi4)[i] = h;
        reinterpret_cast<__nv_bfloat16*>(g_Blo4)[i] =
            __float2bfloat16(w - __bfloat162float(h));
    }
}

// ---------------------------------------------------------------------------
// 1) hetero kernel: blocks [0, Gg) = x@Wr^T half-GEMM -> g_part,
//                   blocks [Gg, ..) = atomic scatter (agg += x[src], deg++)
//    Disjoint pipes (tensor/L1 vs LTS) -> GEMM hides under scatter.
// ---------------------------------------------------------------------------
__global__ __launch_bounds__(256, 2) void hetero_kernel(
    const float* __restrict__ x, const int* __restrict__ ei,
    const float* __restrict__ bl, int N, int E, int Gg)
{
    extern __shared__ char smem[];
    const int tid  = threadIdx.x;
    const int wid  = tid >> 5;
    const int lane = tid & 31;

    if (blockIdx.x >= Gg) {
        // ===== scatter role: 8 warps x 4 edges =====
        const int base = (blockIdx.x - Gg) * 32 + wid * 4;
        const bool act = lane < 24;
        const int c = lane;                   // float4 chunk 0..23

        int srcs[4], dsts[4];
        bool ok[4];
#pragma unroll
        for (int u = 0; u < 4; ++u) {
            int e = base + u;
            ok[u] = e < E;
            srcs[u] = ok[u] ? __ldg(ei + e) : 0;
            dsts[u] = ok[u] ? __ldg(ei + E + e) : 0;
        }
        float4 v[4];
#pragma unroll
        for (int u = 0; u < 4; ++u)
            if (ok[u] && act)
                v[u] = __ldg(reinterpret_cast<const float4*>(
                           x + (size_t)srcs[u] * D) + c);
#pragma unroll
        for (int u = 0; u < 4; ++u)
            if (ok[u] && act) {
                float* p = g_agg + (size_t)dsts[u] * D + c * 4;
                asm volatile("red.global.add.v4.f32 [%0], {%1,%2,%3,%4};"
                             :: "l"(p), "f"(v[u].x), "f"(v[u].y),
                                "f"(v[u].z), "f"(v[u].w) : "memory");
            }
        if (lane == 24) {
#pragma unroll
            for (int u = 0; u < 4; ++u)
                if (ok[u]) atomicAdd(g_deg + dsts[u], 1.0f);
        }
        return;
    }

    // ===== GEMM-R role: g_part = x @ Wr^T + bl =====
    const int m0 = blockIdx.x * 128;
    const int mbase = m0 + wid * 16;

    // stage Wr halves (original chunks 12..23 -> local 0..11, swizzled)
    for (int l = tid; l < 1152; l += 256) {
        int n = l / 12, q = l % 12;
        int so = n * BRS2 + bswz(n, q);
        *reinterpret_cast<uint4*>(smem + so) = g_Bhi4[n * 24 + 12 + q];
        *reinterpret_cast<uint4*>(smem + SM_BLO_OFF + so) = g_Blo4[n * 24 + 12 + q];
    }

    const int g = lane >> 2, t = lane & 3;
    const int r0 = mbase + g, r1 = r0 + 8;
    const bool ok0 = r0 < N, ok1 = r1 < N;
    const float* xp0 = x + (size_t)(ok0 ? r0 : 0) * D;
    const float* xp1 = x + (size_t)(ok1 ? r1 : 0) * D;

    const int lrow8 = lane & 7;
    const int brow  = lrow8 + ((lane >> 4) << 3);
    const int bksel = (lane >> 3) & 1;
    const uint32_t sb = smem_u32(smem);

    float acc[12][4];
#pragma unroll
    for (int j = 0; j < 12; ++j)
#pragma unroll
        for (int r = 0; r < 4; ++r) acc[j][r] = 0.f;

    auto load_raw = [&](int ks, float2* v) {
        const float2 z = make_float2(0.f, 0.f);
        const int col = ks * 16 + 2 * t;
        v[0] = ok0 ? __ldg(reinterpret_cast<const float2*>(xp0 + col))     : z;
        v[1] = ok0 ? __ldg(reinterpret_cast<const float2*>(xp0 + col + 8)) : z;
        v[2] = ok1 ? __ldg(reinterpret_cast<const float2*>(xp1 + col))     : z;
        v[3] = ok1 ? __ldg(reinterpret_cast<const float2*>(xp1 + col + 8)) : z;
    };

    __syncthreads();

    float2 raw[4];
    load_raw(0, raw);

#pragma unroll
    for (int ks = 0; ks < 6; ++ks) {
        float2 nxt[4];
        if (ks < 5) load_raw(ks + 1, nxt);

        float vx[4][2] = {{raw[0].x, raw[0].y}, {raw[2].x, raw[2].y},
                          {raw[1].x, raw[1].y}, {raw[3].x, raw[3].y}};
        uint32_t ahi[4], alo[4];
#pragma unroll
        for (int i = 0; i < 4; ++i) {
            ahi[i] = pack_bf16x2(vx[i][0], vx[i][1]);
            alo[i] = pack_bf16x2(vx[i][0] - __uint_as_float(ahi[i] << 16),
                                 vx[i][1] - __uint_as_float(ahi[i] & 0xffff0000u));
        }

        const int ch = 2 * ks + bksel;
        const uint32_t bOff = brow * BRS2 + bswz(lrow8, ch);

        uint32_t b[6][4];
#pragma unroll
        for (int q = 0; q < 6; ++q)
            LDSM_X4(b[q], sb + bOff + q * 16 * BRS2);
#pragma unroll
        for (int j = 0; j < 12; ++j)
            mma_bf16(acc[j], ahi, b[j >> 1][(j & 1) * 2], b[j >> 1][(j & 1) * 2 + 1]);
#pragma unroll
        for (int j = 0; j < 12; ++j)
            mma_bf16(acc[j], alo, b[j >> 1][(j & 1) * 2], b[j >> 1][(j & 1) * 2 + 1]);

#pragma unroll
        for (int q = 0; q < 6; ++q)
            LDSM_X4(b[q], sb + SM_BLO_OFF + bOff + q * 16 * BRS2);
#pragma unroll
        for (int j = 0; j < 12; ++j)
            mma_bf16(acc[j], ahi, b[j >> 1][(j & 1) * 2], b[j >> 1][(j & 1) * 2 + 1]);

#pragma unroll
        for (int i = 0; i < 4; ++i) raw[i] = nxt[i];
    }

    // epilogue: + bias -> g_part (no relu)
    const int erow = lane >> 2;
    const int ecol = (lane & 3) * 2;
#pragma unroll
    for (int j = 0; j < 12; ++j) {
        int col = j * 8 + ecol;
        float b0 = __ldg(bl + col);
        float b1 = __ldg(bl + col + 1);
        int row0 = mbase + erow;
        if (row0 < N) {
            float2 o = make_float2(acc[j][0] + b0, acc[j][1] + b1);
            *reinterpret_cast<float2*>(g_part + (size_t)row0 * D + col) = o;
        }
        int row1 = row0 + 8;
        if (row1 < N) {
            float2 o = make_float2(acc[j][2] + b0, acc[j][3] + b1);
            *reinterpret_cast<float2*>(g_part + (size_t)row1 * D + col) = o;
        }
    }
}

// ---------------------------------------------------------------------------
// 2) gemmL: out = relu( (agg/deg) @ Wl^T + g_part )
// ---------------------------------------------------------------------------
__global__ __launch_bounds__(256, 2) void gemmL_kernel(
    float* __restrict__ out, int N)
{
    extern __shared__ char smem[];
    const int tid  = threadIdx.x;
    const int wid  = tid >> 5;
    const int lane = tid & 31;
    const int m0 = blockIdx.x * 128;
    const int mbase = m0 + wid * 16;

    // stage Wl halves (original chunks 0..11, swizzled)
    for (int l = tid; l < 1152; l += 256) {
        int n = l / 12, q = l % 12;
        int so = n * BRS2 + bswz(n, q);
        *reinterpret_cast<uint4*>(smem + so) = g_Bhi4[n * 24 + q];
        *reinterpret_cast<uint4*>(smem + SM_BLO_OFF + so) = g_Blo4[n * 24 + q];
    }

    const int g = lane >> 2, t = lane & 3;
    const int r0 = mbase + g, r1 = r0 + 8;
    const bool ok0 = r0 < N, ok1 = r1 < N;
    const float inv0 = ok0 ? 1.0f / fmaxf(__ldg(g_deg + r0), 1.0f) : 1.f;
    const float inv1 = ok1 ? 1.0f / fmaxf(__ldg(g_deg + r1), 1.0f) : 1.f;
    const float* ap0 = g_agg + (size_t)(ok0 ? r0 : 0) * D;
    const float* ap1 = g_agg + (size_t)(ok1 ? r1 : 0) * D;

    const int lrow8 = lane & 7;
    const int brow  = lrow8 + ((lane >> 4) << 3);
    const int bksel = (lane >> 3) & 1;
    const uint32_t sb = smem_u32(smem);

    // init accumulators from g_part (same fragment<->element map as epilogue)
    const int erow = lane >> 2;
    const int ecol = (lane & 3) * 2;
    float acc[12][4];
#pragma unroll
    for (int j = 0; j < 12; ++j) {
        int col = j * 8 + ecol;
        int row0 = mbase + erow, row1 = row0 + 8;
        float2 p0 = (row0 < N)
            ? *reinterpret_cast<const float2*>(g_part + (size_t)row0 * D + col)
            : make_float2(0.f, 0.f);
        float2 p1 = (row1 < N)
            ? *reinterpret_cast<const float2*>(g_part + (size_t)row1 * D + col)
            : make_float2(0.f, 0.f);
        acc[j][0] = p0.x; acc[j][1] = p0.y;
        acc[j][2] = p1.x; acc[j][3] = p1.y;
    }

    auto load_raw = [&](int ks, float2* v) {
        const float2 z = make_float2(0.f, 0.f);
        const int col = ks * 16 + 2 * t;
        v[0] = ok0 ? __ldg(reinterpret_cast<const float2*>(ap0 + col))     : z;
        v[1] = ok0 ? __ldg(reinterpret_cast<const float2*>(ap0 + col + 8)) : z;
        v[2] = ok1 ? __ldg(reinterpret_cast<const float2*>(ap1 + col))     : z;
        v[3] = ok1 ? __ldg(reinterpret_cast<const float2*>(ap1 + col + 8)) : z;
    };

    __syncthreads();

    float2 raw[4];
    load_raw(0, raw);

#pragma unroll
    for (int ks = 0; ks < 6; ++ks) {
        float2 nxt[4];
        if (ks < 5) load_raw(ks + 1, nxt);

        float vx[4][2] = {{raw[0].x * inv0, raw[0].y * inv0},
                          {raw[2].x * inv1, raw[2].y * inv1},
                          {raw[1].x * inv0, raw[1].y * inv0},
                          {raw[3].x * inv1, raw[3].y * inv1}};
        uint32_t ahi[4], alo[4];
#pragma unroll
        for (int i = 0; i < 4; ++i) {
            ahi[i] = pack_bf16x2(vx[i][0], vx[i][1]);
            alo[i] = pack_bf16x2(vx[i][0] - __uint_as_float(ahi[i] << 16),
                                 vx[i][1] - __uint_as_float(ahi[i] & 0xffff0000u));
        }

        const int ch = 2 * ks + bksel;
        const uint32_t bOff = brow * BRS2 + bswz(lrow8, ch);

        uint32_t b[6][4];
#pragma unroll
        for (int q = 0; q < 6; ++q)
            LDSM_X4(b[q], sb + bOff + q * 16 * BRS2);
#pragma unroll
        for (int j = 0; j < 12; ++j)
            mma_bf16(acc[j], ahi, b[j >> 1][(j & 1) * 2], b[j >> 1][(j & 1) * 2 + 1]);
#pragma unroll
        for (int j = 0; j < 12; ++j)
            mma_bf16(acc[j], alo, b[j >> 1][(j & 1) * 2], b[j >> 1][(j & 1) * 2 + 1]);

#pragma unroll
        for (int q = 0; q < 6; ++q)
            LDSM_X4(b[q], sb + SM_BLO_OFF + bOff + q * 16 * BRS2);
#pragma unroll
        for (int j = 0; j < 12; ++j)
            mma_bf16(acc[j], ahi, b[j >> 1][(j & 1) * 2], b[j >> 1][(j & 1) * 2 + 1]);

#pragma unroll
        for (int i = 0; i < 4; ++i) raw[i] = nxt[i];
    }

    // epilogue: relu -> out
#pragma unroll
    for (int j = 0; j < 12; ++j) {
        int col = j * 8 + ecol;
        int row0 = mbase + erow;
        if (row0 < N) {
            float2 o = make_float2(fmaxf(acc[j][0], 0.f), fmaxf(acc[j][1], 0.f));
            *reinterpret_cast<float2*>(out + (size_t)row0 * D + col) = o;
        }
        int row1 = row0 + 8;
        if (row1 < N) {
            float2 o = make_float2(fmaxf(acc[j][2], 0.f), fmaxf(acc[j][3], 0.f));
            *reinterpret_cast<float2*>(out + (size_t)row1 * D + col) = o;
        }
    }
}

// ---------------------------------------------------------------------------
// kernel_launch
// ---------------------------------------------------------------------------
extern "C" void kernel_launch(void* const* d_in, const int* in_sizes, int n_in,
                              void* d_out, int out_size)
{
    const float* x  = (const float*)d_in[0];
    const int*   ei = (const int*)  d_in[1];
    const float* Wl = (const float*)d_in[2];
    const float* bl = (const float*)d_in[3];
    const float* Wr = (const float*)d_in[4];
    float* out = (float*)d_out;

    const int N = in_sizes[0] / D;
    const int E = in_sizes[1] / 2;

    cudaFuncSetAttribute(hetero_kernel,
                         cudaFuncAttributeMaxDynamicSharedMemorySize, SM_HALF_TOTAL);
    cudaFuncSetAttribute(gemmL_kernel,
                         cudaFuncAttributeMaxDynamicSharedMemorySize, SM_HALF_TOTAL);

    prep_kernel<<<2048, 256>>>(Wl, Wr, (N * D) / 4, N);

    const int Gg = (N + 127) / 128;                  // GEMM-R blocks
    const int Sg = (E + 31) / 32;                    // scatter blocks
    hetero_kernel<<<Gg + Sg, 256, SM_HALF_TOTAL>>>(x, ei, bl, N, E, Gg);

    gemmL_kernel<<<Gg, 256, SM_HALF_TOTAL>>>(out, N);
}

// round 14
// speedup vs baseline: 1.9914x; 1.9914x over previous
#include <cuda_runtime.h>
#include <cuda_bf16.h>
#include <cstdint>

// Problem constants.
#define D    96      // D_IN == D_OUT
#define K2   192     // concat K = 2*D
#define MAXN 50000

// Scratch (no cudaMalloc allowed). uint4 typing guarantees 16B alignment.
__device__ float g_agg[(size_t)MAXN * D];        // neighbor-sum
__device__ float g_deg[MAXN];                    // in-degree (float)
__device__ uint4 g_Bhi4[(D * K2 * 2) / 16];      // [96][24 uint4] Wcat hi
__device__ uint4 g_Blo4[(D * K2 * 2) / 16];      // [96][24 uint4] Wcat lo

// ---------------------------------------------------------------------------
// helpers
// ---------------------------------------------------------------------------
__device__ __forceinline__ uint32_t smem_u32(const void* p) {
    uint32_t a;
    asm("{ .reg .u64 t; cvta.to.shared.u64 t, %1; cvt.u32.u64 %0, t; }"
        : "=r"(a) : "l"(p));
    return a;
}

__device__ __forceinline__ uint32_t pack_bf16x2(float a, float b) {
    uint32_t r;
    asm("cvt.rn.bf16x2.f32 %0, %1, %2;" : "=r"(r) : "f"(b), "f"(a));
    return r;
}

#define LDSM_X4(r, addr)                                                      \
    asm volatile("ldmatrix.sync.aligned.m8n8.x4.shared.b16 "                  \
                 "{%0,%1,%2,%3}, [%4];"                                       \
                 : "=r"((r)[0]), "=r"((r)[1]), "=r"((r)[2]), "=r"((r)[3])     \
                 : "r"(addr))

__device__ __forceinline__ void mma_bf16(float* c, const uint32_t* a,
                                         uint32_t b0, uint32_t b1) {
    asm volatile(
        "mma.sync.aligned.m16n8k16.row.col.f32.bf16.bf16.f32 "
        "{%0,%1,%2,%3}, {%4,%5,%6,%7}, {%8,%9}, {%0,%1,%2,%3};"
        : "+f"(c[0]), "+f"(c[1]), "+f"(c[2]), "+f"(c[3])
        : "r"(a[0]), "r"(a[1]), "r"(a[2]), "r"(a[3]), "r"(b0), "r"(b1));
}

// ---------------------------------------------------------------------------
// 0) prep: zero agg+deg, split W = [Wl|Wr] into bf16 hi/lo
//    W-split confined to the first 72 blocks (18432 elems); all blocks zero.
// ---------------------------------------------------------------------------
__global__ __launch_bounds__(256) void prep_kernel(
    const float* __restrict__ Wl, const float* __restrict__ Wr,
    int n_agg4, int n_deg)
{
    int idx = blockIdx.x * blockDim.x + threadIdx.x;
    int stride = gridDim.x * blockDim.x;
    float4* a4 = reinterpret_cast<float4*>(g_agg);
    const float4 z4 = make_float4(0.f, 0.f, 0.f, 0.f);
    for (int i = idx; i < n_agg4; i += stride)
        a4[i] = z4;
    for (int i = idx; i < n_deg; i += stride)
        g_deg[i] = 0.f;
    if (idx < D * K2) {                    // one element per thread, no loop
        int r = idx / K2, k = idx - r * K2;
        float w = (k < D) ? __ldg(Wl + r * D + k) : __ldg(Wr + r * D + (k - D));
        __nv_bfloat16 h = __float2bfloat16(w);
        reinterpret_cast<__nv_bfloat16*>(g_Bhi4)[idx] = h;
        reinterpret_cast<__nv_bfloat16*>(g_Blo4)[idx] =
            __float2bfloat16(w - __bfloat162float(h));
    }
}

// ---------------------------------------------------------------------------
// 1) scatter: agg[dst] += x[src]; deg[dst] += 1   (red.global.add.v4.f32)
//    EXACT R8 configuration (proven LTS-cap performance).
// ---------------------------------------------------------------------------
__global__ __launch_bounds__(192) void scatter_kernel(
    const float* __restrict__ x, const int* __restrict__ ei, int E)
{
    int e = blockIdx.x * 8 + threadIdx.y;
    if (e >= E) return;
    int c = threadIdx.x;                 // 0..23
    int src = __ldg(ei + e);
    int dst = __ldg(ei + E + e);

    float4 v = *reinterpret_cast<const float4*>(x + (size_t)src * D + c * 4);
    float* p = g_agg + (size_t)dst * D + c * 4;
    asm volatile("red.global.add.v4.f32 [%0], {%1,%2,%3,%4};"
                 :: "l"(p), "f"(v.x), "f"(v.y), "f"(v.z), "f"(v.w)
                 : "memory");
    if (c == 0) atomicAdd(g_deg + dst, 1.0f);
}

// ---------------------------------------------------------------------------
// 2) GEMM: out = relu([ (agg/deg) | x] @ [Wl|Wr]^T + bl)
//    R8 design; deg reciprocal folded in (recip kernel deleted).
// ---------------------------------------------------------------------------
#define BRS 384
#define SM_BLO_OFF (96 * BRS)
#define SM_TOTAL (2 * 96 * BRS)      // 73728 B

__device__ __forceinline__ int bswz(int row, int chunk) {
    return ((chunk & ~7) | ((chunk ^ row) & 7)) << 4;
}

__global__ __launch_bounds__(256, 2) void fused_gemm_kernel(
    const float* __restrict__ x, const float* __restrict__ bl,
    float* __restrict__ out, int N)
{
    extern __shared__ char smem[];

    const int tid  = threadIdx.x;
    const int wid  = tid >> 5;
    const int lane = tid & 31;
    const int m0   = blockIdx.x * 128;
    const int mbase = m0 + wid * 16;

    for (int l = tid; l < 2304; l += 256) {
        int n = l / 24, q = l % 24;
        int so = n * BRS + bswz(n, q);
        *reinterpret_cast<uint4*>(smem + so) = g_Bhi4[l];
        *reinterpret_cast<uint4*>(smem + SM_BLO_OFF + so) = g_Blo4[l];
    }

    const int g = lane >> 2, t = lane & 3;
    const int r0 = mbase + g, r1 = r0 + 8;
    const bool ok0 = r0 < N, ok1 = r1 < N;
    const float inv0 = ok0 ? 1.0f / fmaxf(__ldg(g_deg + r0), 1.0f) : 1.f;
    const float inv1 = ok1 ? 1.0f / fmaxf(__ldg(g_deg + r1), 1.0f) : 1.f;
    const float* aggp0 = g_agg + (size_t)(ok0 ? r0 : 0) * D;
    const float* aggp1 = g_agg + (size_t)(ok1 ? r1 : 0) * D;
    const float* xp0   = x     + (size_t)(ok0 ? r0 : 0) * D;
    const float* xp1   = x     + (size_t)(ok1 ? r1 : 0) * D;

    const int lrow8  = lane & 7;
    const int brow   = lrow8 + ((lane >> 4) << 3);
    const int bksel  = (lane >> 3) & 1;
    const uint32_t sb = smem_u32(smem);

    float acc[12][4];
#pragma unroll
    for (int j = 0; j < 12; ++j)
#pragma unroll
        for (int r = 0; r < 4; ++r) acc[j][r] = 0.f;

    auto load_raw = [&](int ks, float2* v) {
        const float2 z = make_float2(0.f, 0.f);
        const int col = (ks < 6) ? ks * 16 + 2 * t : (ks - 6) * 16 + 2 * t;
        const float* p0 = (ks < 6) ? aggp0 : xp0;
        const float* p1 = (ks < 6) ? aggp1 : xp1;
        v[0] = ok0 ? __ldg(reinterpret_cast<const float2*>(p0 + col))     : z;
        v[1] = ok0 ? __ldg(reinterpret_cast<const float2*>(p0 + col + 8)) : z;
        v[2] = ok1 ? __ldg(reinterpret_cast<const float2*>(p1 + col))     : z;
        v[3] = ok1 ? __ldg(reinterpret_cast<const float2*>(p1 + col + 8)) : z;
    };

    __syncthreads();

    float2 raw[4];
    load_raw(0, raw);

#pragma unroll
    for (int ks = 0; ks < 12; ++ks) {
        float2 nxt[4];
        if (ks < 11) load_raw(ks + 1, nxt);

        const float sA = (ks < 6) ? inv0 : 1.f;
        const float sB = (ks < 6) ? inv1 : 1.f;
        float vx[4][2] = {{raw[0].x * sA, raw[0].y * sA},
                          {raw[2].x * sB, raw[2].y * sB},
                          {raw[1].x * sA, raw[1].y * sA},
                          {raw[3].x * sB, raw[3].y * sB}};
        uint32_t ahi[4], alo[4];
#pragma unroll
        for (int i = 0; i < 4; ++i) {
            ahi[i] = pack_bf16x2(vx[i][0], vx[i][1]);
            alo[i] = pack_bf16x2(vx[i][0] - __uint_as_float(ahi[i] << 16),
                                 vx[i][1] - __uint_as_float(ahi[i] & 0xffff0000u));
        }

        const int ch = 2 * ks + bksel;
        const uint32_t bOff = brow * BRS + bswz(lrow8, ch);

        uint32_t b[6][4];
#pragma unroll
        for (int q = 0; q < 6; ++q)
            LDSM_X4(b[q], sb + bOff + q * 16 * BRS);
#pragma unroll
        for (int j = 0; j < 12; ++j)
            mma_bf16(acc[j], ahi, b[j >> 1][(j & 1) * 2], b[j >> 1][(j & 1) * 2 + 1]);
#pragma unroll
        for (int j = 0; j < 12; ++j)
            mma_bf16(acc[j], alo, b[j >> 1][(j & 1) * 2], b[j >> 1][(j & 1) * 2 + 1]);

#pragma unroll
        for (int q = 0; q < 6; ++q)
            LDSM_X4(b[q], sb + SM_BLO_OFF + bOff + q * 16 * BRS);
#pragma unroll
        for (int j = 0; j < 12; ++j)
            mma_bf16(acc[j], ahi, b[j >> 1][(j & 1) * 2], b[j >> 1][(j & 1) * 2 + 1]);

#pragma unroll
        for (int i = 0; i < 4; ++i) raw[i] = nxt[i];
    }

    const int erow = lane >> 2;
    const int ecol = (lane & 3) * 2;
#pragma unroll
    for (int j = 0; j < 12; ++j) {
        int col = j * 8 + ecol;
        float b0 = __ldg(bl + col);
        float b1 = __ldg(bl + col + 1);
        int row0 = mbase + erow;
        if (row0 < N) {
            float2 o = make_float2(fmaxf(acc[j][0] + b0, 0.f),
                                   fmaxf(acc[j][1] + b1, 0.f));
            *reinterpret_cast<float2*>(out + (size_t)row0 * D + col) = o;
        }
        int row1 = row0 + 8;
        if (row1 < N) {
            float2 o = make_float2(fmaxf(acc[j][2] + b0, 0.f),
                                   fmaxf(acc[j][3] + b1, 0.f));
            *reinterpret_cast<float2*>(out + (size_t)row1 * D + col) = o;
        }
    }
}

// ---------------------------------------------------------------------------
// kernel_launch
// ---------------------------------------------------------------------------
extern "C" void kernel_launch(void* const* d_in, const int* in_sizes, int n_in,
                              void* d_out, int out_size)
{
    const float* x  = (const float*)d_in[0];
    const int*   ei = (const int*)  d_in[1];
    const float* Wl = (const float*)d_in[2];
    const float* bl = (const float*)d_in[3];
    const float* Wr = (const float*)d_in[4];
    float* out = (float*)d_out;

    const int N = in_sizes[0] / D;
    const int E = in_sizes[1] / 2;

    cudaFuncSetAttribute(fused_gemm_kernel,
                         cudaFuncAttributeMaxDynamicSharedMemorySize, SM_TOTAL);

    prep_kernel<<<4736, 256>>>(Wl, Wr, (N * D) / 4, N);

    dim3 sblk(24, 8);
    scatter_kernel<<<(E + 7) / 8, sblk>>>(x, ei, E);

    fused_gemm_kernel<<<(N + 127) / 128, 256, SM_TOTAL>>>(x, bl, out, N);
}

// round 17
// speedup vs baseline: 2.0836x; 1.0463x over previous
#include <cuda_runtime.h>
#include <cuda_fp16.h>
#include <cstdint>

// Problem constants.
#define D    96      // D_IN == D_OUT
#define K2   192     // concat K = 2*D
#define MAXN 50000

// Scratch (no cudaMalloc allowed). uint4 typing guarantees 16B alignment.
__device__ float g_agg[(size_t)MAXN * D];        // neighbor-sum
__device__ float g_deg[MAXN];                    // in-degree (float)
__device__ uint4 g_Bf4[(D * K2 * 2) / 16];       // [96][192] fp16 Wcat

// ---------------------------------------------------------------------------
// helpers
// ---------------------------------------------------------------------------
__device__ __forceinline__ uint32_t smem_u32(const void* p) {
    uint32_t a;
    asm("{ .reg .u64 t; cvta.to.shared.u64 t, %1; cvt.u32.u64 %0, t; }"
        : "=r"(a) : "l"(p));
    return a;
}

// pack two f32 into f16x2 (lo half = a, hi half = b), round-to-nearest
__device__ __forceinline__ uint32_t pack_f16x2(float a, float b) {
    uint32_t r;
    asm("cvt.rn.f16x2.f32 %0, %1, %2;" : "=r"(r) : "f"(b), "f"(a));
    return r;
}

__device__ __forceinline__ float2 unpack_f16x2(uint32_t v) {
    __half2 h = *reinterpret_cast<__half2*>(&v);
    return __half22float2(h);
}

#define LDSM_X4(r, addr)                                                      \
    asm volatile("ldmatrix.sync.aligned.m8n8.x4.shared.b16 "                  \
                 "{%0,%1,%2,%3}, [%4];"                                       \
                 : "=r"((r)[0]), "=r"((r)[1]), "=r"((r)[2]), "=r"((r)[3])     \
                 : "r"(addr))

__device__ __forceinline__ void mma_f16(float* c, const uint32_t* a,
                                        uint32_t b0, uint32_t b1) {
    asm volatile(
        "mma.sync.aligned.m16n8k16.row.col.f32.f16.f16.f32 "
        "{%0,%1,%2,%3}, {%4,%5,%6,%7}, {%8,%9}, {%0,%1,%2,%3};"
        : "+f"(c[0]), "+f"(c[1]), "+f"(c[2]), "+f"(c[3])
        : "r"(a[0]), "r"(a[1]), "r"(a[2]), "r"(a[3]), "r"(b0), "r"(b1));
}

// ---------------------------------------------------------------------------
// 0) prep: zero agg+deg, W = [Wl|Wr] -> fp16 (single precision level for B)
// ---------------------------------------------------------------------------
__global__ __launch_bounds__(256) void prep_kernel(
    const float* __restrict__ Wl, const float* __restrict__ Wr,
    int n_agg4, int n_deg)
{
    int idx = blockIdx.x * blockDim.x + threadIdx.x;
    int stride = gridDim.x * blockDim.x;
    float4* a4 = reinterpret_cast<float4*>(g_agg);
    const float4 z4 = make_float4(0.f, 0.f, 0.f, 0.f);
    for (int i = idx; i < n_agg4; i += stride)
        a4[i] = z4;
    for (int i = idx; i < n_deg; i += stride)
        g_deg[i] = 0.f;
    if (idx < D * K2) {
        int r = idx / K2, k = idx - r * K2;
        float w = (k < D) ? __ldg(Wl + r * D + k) : __ldg(Wr + r * D + (k - D));
        reinterpret_cast<__half*>(g_Bf4)[idx] = __float2half_rn(w);
    }
}

// ---------------------------------------------------------------------------
// 1) scatter: agg[dst] += x[src]; deg[dst] += 1   (red.global.add.v4.f32)
//    EXACT R8 configuration (proven LTS-cap performance).
// ---------------------------------------------------------------------------
__global__ __launch_bounds__(192) void scatter_kernel(
    const float* __restrict__ x, const int* __restrict__ ei, int E)
{
    int e = blockIdx.x * 8 + threadIdx.y;
    if (e >= E) return;
    int c = threadIdx.x;                 // 0..23
    int src = __ldg(ei + e);
    int dst = __ldg(ei + E + e);

    float4 v = *reinterpret_cast<const float4*>(x + (size_t)src * D + c * 4);
    float* p = g_agg + (size_t)dst * D + c * 4;
    asm volatile("red.global.add.v4.f32 [%0], {%1,%2,%3,%4};"
                 :: "l"(p), "f"(v.x), "f"(v.y), "f"(v.z), "f"(v.w)
                 : "memory");
    if (c == 0) atomicAdd(g_deg + dst, 1.0f);
}

// ---------------------------------------------------------------------------
// 2) GEMM: out = relu([ (agg/deg) | x] @ [Wl|Wr]^T + bl)
//    A = Ahi + Alo (fp16 split in registers, ~22-bit effective), B single
//    fp16 in one 36.9 KB swizzled smem buffer. Per k-step: A LDG prefetch,
//    6 LDSM, 24 MMA (hi then lo). fp32 accumulators.
// ---------------------------------------------------------------------------
#define BRS 384

__device__ __forceinline__ int bswz(int row, int chunk) {
    return ((chunk & ~7) | ((chunk ^ row) & 7)) << 4;
}

__global__ __launch_bounds__(256, 2) void fused_gemm_kernel(
    const float* __restrict__ x, const float* __restrict__ bl,
    float* __restrict__ out, int N)
{
    __shared__ char smem[96 * BRS];      // 36864 B

    const int tid  = threadIdx.x;
    const int wid  = tid >> 5;
    const int lane = tid & 31;
    const int m0   = blockIdx.x * 128;
    const int mbase = m0 + wid * 16;

    // stage B (fp16, swizzled): 96 rows x 24 uint4 chunks
    for (int l = tid; l < 2304; l += 256) {
        int n = l / 24, q = l % 24;
        *reinterpret_cast<uint4*>(smem + n * BRS + bswz(n, q)) = g_Bf4[l];
    }

    const int g = lane >> 2, t = lane & 3;
    const int r0 = mbase + g, r1 = r0 + 8;
    const bool ok0 = r0 < N, ok1 = r1 < N;
    const float inv0 = ok0 ? 1.0f / fmaxf(__ldg(g_deg + r0), 1.0f) : 1.f;
    const float inv1 = ok1 ? 1.0f / fmaxf(__ldg(g_deg + r1), 1.0f) : 1.f;
    const float* aggp0 = g_agg + (size_t)(ok0 ? r0 : 0) * D;
    const float* aggp1 = g_agg + (size_t)(ok1 ? r1 : 0) * D;
    const float* xp0   = x     + (size_t)(ok0 ? r0 : 0) * D;
    const float* xp1   = x     + (size_t)(ok1 ? r1 : 0) * D;

    const int lrow8  = lane & 7;
    const int brow   = lrow8 + ((lane >> 4) << 3);
    const int bksel  = (lane >> 3) & 1;
    const uint32_t sb = smem_u32(smem);

    float acc[12][4];
#pragma unroll
    for (int j = 0; j < 12; ++j)
#pragma unroll
        for (int r = 0; r < 4; ++r) acc[j][r] = 0.f;

    auto load_raw = [&](int ks, float2* v) {
        const float2 z = make_float2(0.f, 0.f);
        const int col = (ks < 6) ? ks * 16 + 2 * t : (ks - 6) * 16 + 2 * t;
        const float* p0 = (ks < 6) ? aggp0 : xp0;
        const float* p1 = (ks < 6) ? aggp1 : xp1;
        v[0] = ok0 ? __ldg(reinterpret_cast<const float2*>(p0 + col))     : z;
        v[1] = ok0 ? __ldg(reinterpret_cast<const float2*>(p0 + col + 8)) : z;
        v[2] = ok1 ? __ldg(reinterpret_cast<const float2*>(p1 + col))     : z;
        v[3] = ok1 ? __ldg(reinterpret_cast<const float2*>(p1 + col + 8)) : z;
    };

    __syncthreads();

    float2 raw[4];
    load_raw(0, raw);

#pragma unroll
    for (int ks = 0; ks < 12; ++ks) {
        float2 nxt[4];
        if (ks < 11) load_raw(ks + 1, nxt);

        const float sA = (ks < 6) ? inv0 : 1.f;
        const float sB = (ks < 6) ? inv1 : 1.f;
        float vx[4][2] = {{raw[0].x * sA, raw[0].y * sA},
                          {raw[2].x * sB, raw[2].y * sB},
                          {raw[1].x * sA, raw[1].y * sA},
                          {raw[3].x * sB, raw[3].y * sB}};
        uint32_t ahi[4], alo[4];
#pragma unroll
        for (int i = 0; i < 4; ++i) {
            ahi[i] = pack_f16x2(vx[i][0], vx[i][1]);
            float2 back = unpack_f16x2(ahi[i]);
            alo[i] = pack_f16x2(vx[i][0] - back.x, vx[i][1] - back.y);
        }

        const int ch = 2 * ks + bksel;
        const uint32_t bAddr = sb + brow * BRS + bswz(lrow8, ch);

        uint32_t b[6][4];
#pragma unroll
        for (int q = 0; q < 6; ++q)
            LDSM_X4(b[q], bAddr + q * 16 * BRS);
#pragma unroll
        for (int j = 0; j < 12; ++j)
            mma_f16(acc[j], ahi, b[j >> 1][(j & 1) * 2], b[j >> 1][(j & 1) * 2 + 1]);
#pragma unroll
        for (int j = 0; j < 12; ++j)
            mma_f16(acc[j], alo, b[j >> 1][(j & 1) * 2], b[j >> 1][(j & 1) * 2 + 1]);

#pragma unroll
        for (int i = 0; i < 4; ++i) raw[i] = nxt[i];
    }

    const int erow = lane >> 2;
    const int ecol = (lane & 3) * 2;
#pragma unroll
    for (int j = 0; j < 12; ++j) {
        int col = j * 8 + ecol;
        float b0 = __ldg(bl + col);
        float b1 = __ldg(bl + col + 1);
        int row0 = mbase + erow;
        if (row0 < N) {
            float2 o = make_float2(fmaxf(acc[j][0] + b0, 0.f),
                                   fmaxf(acc[j][1] + b1, 0.f));
            *reinterpret_cast<float2*>(out + (size_t)row0 * D + col) = o;
        }
        int row1 = row0 + 8;
        if (row1 < N) {
            float2 o = make_float2(fmaxf(acc[j][2] + b0, 0.f),
                                   fmaxf(acc[j][3] + b1, 0.f));
            *reinterpret_cast<float2*>(out + (size_t)row1 * D + col) = o;
        }
    }
}

// ---------------------------------------------------------------------------
// kernel_launch
// ---------------------------------------------------------------------------
extern "C" void kernel_launch(void* const* d_in, const int* in_sizes, int n_in,
                              void* d_out, int out_size)
{
    const float* x  = (const float*)d_in[0];
    const int*   ei = (const int*)  d_in[1];
    const float* Wl = (const float*)d_in[2];
    const float* bl = (const float*)d_in[3];
    const float* Wr = (const float*)d_in[4];
    float* out = (float*)d_out;

    const int N = in_sizes[0] / D;
    const int E = in_sizes[1] / 2;

    prep_kernel<<<4736, 256>>>(Wl, Wr, (N * D) / 4, N);

    dim3 sblk(24, 8);
    scatter_kernel<<<(E + 7) / 8, sblk>>>(x, ei, E);

    fused_gemm_kernel<<<(N + 127) / 128, 256>>>(x, bl, out, N);
}